// round 5
// baseline (speedup 1.0000x reference)
#include <cuda_runtime.h>

#define NROWS 32768
#define DIM   256
#define NE    256
#define NQ    4
#define KP    4096

#define OFF_MEAN  (NROWS*DIM)            // 8388608
#define OFF_OUTER (NROWS*DIM + 1)
#define OFF_IDX   (NROWS*DIM + 1 + NQ)   // 8388613

typedef unsigned long long ull;

// ---------------- device scratch (no allocs allowed) ----------------
__device__ float  g_RES[NROWS*DIM];     // current residual
__device__ float  g_XN [NROWS*DIM];     // normalized residual
__device__ float  g_RR [NROWS];         // ||residual||^2 per row (pre-eps)
__device__ float  g_Q  [KP*DIM];        // gathered query rows xn[i1]
__device__ float2 g_CTP[NQ*128*NE];     // codebook, d-paired + transposed: [q][dpair][entry]
__device__ float  g_CE [NQ*NE];         // ||e||^2
__device__ float  g_SEXP[KP];           // sum of exp(sim) per pair
__device__ float  g_POS [KP];           // pos logits
__device__ float  g_VQ  [NQ];           // sum of squared new residual per stage

// ---------------- helpers ----------------
__device__ __forceinline__ ull bc2(float a) {
    ull r; asm("mov.b64 %0, {%1, %1};" : "=l"(r) : "f"(a)); return r;
}
__device__ __forceinline__ float2 u2f(ull u) {
    float2 f;
    f.x = __uint_as_float((unsigned)(u & 0xffffffffu));
    f.y = __uint_as_float((unsigned)(u >> 32));
    return f;
}
__device__ __forceinline__ void fma2(ull &acc, ull a, ull b) {
    asm("fma.rn.f32x2 %0, %1, %2, %0;" : "+l"(acc) : "l"(a), "l"(b));
}

// block reduce (256 threads), result valid on thread 0
__device__ __forceinline__ float blockReduceSum256(float v, float* sbuf) {
    #pragma unroll
    for (int o = 16; o; o >>= 1) v += __shfl_down_sync(0xffffffffu, v, o);
    int w = threadIdx.x >> 5, l = threadIdx.x & 31;
    if (l == 0) sbuf[w] = v;
    __syncthreads();
    if (w == 0) {
        v = (l < 8) ? sbuf[l] : 0.f;
        #pragma unroll
        for (int o = 4; o; o >>= 1) v += __shfl_down_sync(0xffffffffu, v, o);
    }
    return v;
}

// ---------------- kernels ----------------

// copy x -> residual, zero VQ accumulators
__global__ void k_init(const float* __restrict__ x) {
    int i = blockIdx.x * 256 + threadIdx.x;
    ((float4*)g_RES)[i] = ((const float4*)x)[i];
    if (i < NQ) g_VQ[i] = 0.f;
}

// per-entry ||e||^2 and d-paired transposed codebook
__global__ void k_prep(const float* __restrict__ CB) {
    __shared__ float sbuf[8];
    int q = blockIdx.y, j = blockIdx.x, d = threadIdx.x;
    const float* row = CB + ((size_t)q * NE + j) * DIM;
    float v = row[d];
    float s = blockReduceSum256(v * v, sbuf);
    if (d == 0) g_CE[q * NE + j] = s;
    if (d < 128) {
        float2 p; p.x = row[2*d]; p.y = row[2*d + 1];
        g_CTP[(q * 128 + d) * NE + j] = p;
    }
}

// row L2-normalize: XN = RES * rsqrt(sum^2 + 1e-12); also stash ||r||^2
__global__ void k_norm() {
    __shared__ float sbuf[8];
    __shared__ float stot;
    int row = blockIdx.x;
    float v = g_RES[(size_t)row * DIM + threadIdx.x];
    float s = blockReduceSum256(v * v, sbuf);
    if (threadIdx.x == 0) { stot = s; g_RR[row] = s; }
    __syncthreads();
    float inv = rsqrtf(stot + 1e-12f);
    g_XN[(size_t)row * DIM + threadIdx.x] = v * inv;
}

// gather queries, compute pos, zero SEXP
__global__ void k_gather(const int* __restrict__ p1, const int* __restrict__ p2) {
    __shared__ float sbuf[8];
    int k = blockIdx.x;
    int i1 = p1[k], i2 = p2[k];
    float a = g_XN[(size_t)i1 * DIM + threadIdx.x];
    float b = g_XN[(size_t)i2 * DIM + threadIdx.x];
    g_Q[(size_t)k * DIM + threadIdx.x] = a;
    float s = blockReduceSum256(a * b, sbuf);
    if (threadIdx.x == 0) { g_POS[k] = s * 10.f; g_SEXP[k] = 0.f; }
}

// main GEMM + sum-of-exp: 128x128 tile, 8x8 per thread via packed f32x2 FMA
__global__ void __launch_bounds__(256) k_lse() {
    __shared__ float As[16][132];
    __shared__ float Bs[16][132];
    __shared__ float red[128 * 16];

    int tid = threadIdx.x;
    int bm = blockIdx.y;       // query tile (32)
    int bn = blockIdx.x;       // key tile   (256)
    int tr = tid >> 4, tc = tid & 15;

    ull acc[8][4];
    #pragma unroll
    for (int i = 0; i < 8; i++)
        #pragma unroll
        for (int j = 0; j < 4; j++) acc[i][j] = 0ull;

    const float* Ab = g_Q  + (size_t)(bm * 128) * DIM;
    const float* Bb = g_XN + (size_t)(bn * 128) * DIM;

    for (int k0 = 0; k0 < DIM; k0 += 16) {
        #pragma unroll
        for (int i = 0; i < 2; i++) {
            int lin = tid + i * 256;
            int row = lin >> 2, c4 = lin & 3;
            float4 va = *(const float4*)(Ab + (size_t)row * DIM + k0 + c4 * 4);
            As[c4*4+0][row] = va.x; As[c4*4+1][row] = va.y;
            As[c4*4+2][row] = va.z; As[c4*4+3][row] = va.w;
            float4 vb = *(const float4*)(Bb + (size_t)row * DIM + k0 + c4 * 4);
            Bs[c4*4+0][row] = vb.x; Bs[c4*4+1][row] = vb.y;
            Bs[c4*4+2][row] = vb.z; Bs[c4*4+3][row] = vb.w;
        }
        __syncthreads();
        #pragma unroll
        for (int kk = 0; kk < 16; kk++) {
            float4 a0 = *(const float4*)&As[kk][tr * 8];
            float4 a1 = *(const float4*)&As[kk][tr * 8 + 4];
            ull bv[4];
            #pragma unroll
            for (int j = 0; j < 4; j++)
                bv[j] = *(const ull*)&Bs[kk][tc * 8 + j * 2];
            ull ap[8] = { bc2(a0.x), bc2(a0.y), bc2(a0.z), bc2(a0.w),
                          bc2(a1.x), bc2(a1.y), bc2(a1.z), bc2(a1.w) };
            #pragma unroll
            for (int i = 0; i < 8; i++)
                #pragma unroll
                for (int j = 0; j < 4; j++)
                    fma2(acc[i][j], ap[i], bv[j]);
        }
        __syncthreads();
    }

    // epilogue: exp + row sums
    float rsum[8];
    #pragma unroll
    for (int i = 0; i < 8; i++) rsum[i] = 0.f;
    #pragma unroll
    for (int i = 0; i < 8; i++)
        #pragma unroll
        for (int j = 0; j < 4; j++) {
            float2 f = u2f(acc[i][j]);
            rsum[i] += __expf(10.f * f.x) + __expf(10.f * f.y);
        }

    #pragma unroll
    for (int i = 0; i < 8; i++) red[(tr * 8 + i) * 16 + tc] = rsum[i];
    __syncthreads();
    if (tid < 128) {
        float s = 0.f;
        #pragma unroll
        for (int t = 0; t < 16; t++) s += red[tid * 16 + t];
        atomicAdd(&g_SEXP[bm * 128 + tid], s);
    }
}

// outer loss = mean(log(SEXP) - POS)
__global__ void k_outer(float* __restrict__ out, int q) {
    __shared__ float sbuf[8];
    float acc = 0.f;
    for (int k = threadIdx.x; k < KP; k += 256)
        acc += logf(g_SEXP[k]) - g_POS[k];
    float s = blockReduceSum256(acc, sbuf);
    if (threadIdx.x == 0) out[OFF_OUTER + q] = s / (float)KP;
}

// quantize 32 rows per block: argmin over 256 entries + residual/xq update.
// Distance replicates the reference's rounding profile:
//   d2 = fl( fl(rr - 2*dot) + ee )  with fl(rr - 2*dot) = fmaf(-2, dot, rr)
// (the x2 is exact, so the FMA's single rounding == the reference's round-once
// subtract). Argmin ties at equal fp32 d2 resolve to the lowest index, matching
// jnp.argmin.
__global__ void __launch_bounds__(256) k_quant(const float* __restrict__ CB,
                                               float* __restrict__ out,
                                               int q, int first) {
    __shared__ float rs[32][DIM];
    __shared__ ull   wmin[32][8];
    __shared__ int   idxs[32];
    __shared__ float sbuf[8];
    __shared__ float rr_s[32];

    int tid = threadIdx.x;
    int i0 = blockIdx.x * 32;

    // stage rows into smem
    #pragma unroll
    for (int i = 0; i < 8; i++) {
        int lin = tid + i * 256;        // float4 index; 64 float4 per row
        int m = lin >> 6, c = lin & 63;
        ((float4*)&rs[m][0])[c] = *(const float4*)(g_RES + (size_t)(i0 + m) * DIM + c * 4);
    }
    if (tid < 32) rr_s[tid] = g_RR[i0 + tid];
    __syncthreads();

    int j = tid;  // this thread's codebook entry
    ull dot2[32];
    #pragma unroll
    for (int m = 0; m < 32; m++) dot2[m] = 0ull;

    const float2* ctp = g_CTP + (size_t)q * 128 * NE;
    #pragma unroll 2
    for (int dpc = 0; dpc < 32; dpc++) {
        ull ct[4];
        #pragma unroll
        for (int c = 0; c < 4; c++)
            ct[c] = *(const ull*)&ctp[(dpc * 4 + c) * NE + j];
        #pragma unroll
        for (int m = 0; m < 32; m++) {
            #pragma unroll
            for (int c = 0; c < 4; c++) {
                ull r2 = *(const ull*)&rs[m][(dpc * 4 + c) * 2];
                fma2(dot2[m], r2, ct[c]);
            }
        }
    }

    float ce = g_CE[q * NE + j];
    #pragma unroll
    for (int m = 0; m < 32; m++) {
        float2 f = u2f(dot2[m]);
        float dotv = f.x + f.y;
        float t1 = fmaf(-2.f, dotv, rr_s[m]);   // fl(rr - 2*dot), single rounding
        float d2 = t1 + ce;                     // fl(t1 + ee)
        unsigned u = __float_as_uint(d2);
        u = (u & 0x80000000u) ? ~u : (u | 0x80000000u);
        ull key = ((ull)u << 32) | (ull)(unsigned)j;
        #pragma unroll
        for (int o = 16; o; o >>= 1) {
            ull other = __shfl_down_sync(0xffffffffu, key, o);
            if (other < key) key = other;
        }
        if ((tid & 31) == 0) wmin[m][tid >> 5] = key;
    }
    __syncthreads();

    if (tid < 32) {
        ull best = wmin[tid][0];
        #pragma unroll
        for (int t = 1; t < 8; t++) if (wmin[tid][t] < best) best = wmin[tid][t];
        int id = (int)(best & 0xffu);
        idxs[tid] = id;
        out[OFF_IDX + (size_t)(i0 + tid) * NQ + q] = (float)id;
    }
    __syncthreads();

    // residual / x_q update + loss accumulation
    const float* cb = CB + (size_t)q * NE * DIM;
    float ssq = 0.f;
    #pragma unroll 4
    for (int m = 0; m < 32; m++) {
        float cv = cb[(size_t)idxs[m] * DIM + tid];
        float nr = rs[m][tid] - cv;
        size_t go = (size_t)(i0 + m) * DIM + tid;
        g_RES[go] = nr;
        out[go] = first ? cv : (out[go] + cv);
        ssq += nr * nr;
    }
    float st = blockReduceSum256(ssq, sbuf);
    if (tid == 0) atomicAdd(&g_VQ[q], st);
}

__global__ void k_vqmean(float* __restrict__ out) {
    if (threadIdx.x == 0) {
        float s = g_VQ[0] + g_VQ[1] + g_VQ[2] + g_VQ[3];
        out[OFF_MEAN] = s * (1.25f / (4.f * (float)NROWS * (float)DIM));
    }
}

// ---------------- launch ----------------
extern "C" void kernel_launch(void* const* d_in, const int* in_sizes, int n_in,
                              void* d_out, int out_size) {
    const float* x  = (const float*)d_in[0];
    const float* cb = (const float*)d_in[1];
    const int*   p1 = (const int*)d_in[2];
    const int*   p2 = (const int*)d_in[3];
    float* out = (float*)d_out;

    k_init<<<NROWS * DIM / 4 / 256, 256>>>(x);
    k_prep<<<dim3(NE, NQ), 256>>>(cb);
    for (int q = 0; q < NQ; q++) {
        k_norm<<<NROWS, 256>>>();
        k_gather<<<KP, 256>>>(p1, p2);
        k_lse<<<dim3(NROWS / 128, KP / 128), 256>>>();
        k_outer<<<1, 256>>>(out, q);
        k_quant<<<NROWS / 32, 256>>>(cb, out, q, q == 0);
    }
    k_vqmean<<<1, 32>>>(out);
}

// round 8
// speedup vs baseline: 3.6916x; 3.6916x over previous
#include <cuda_runtime.h>
#include <cuda_bf16.h>

#define NROWS 32768
#define DIM   256
#define NE    256
#define NQ    4
#define KP    4096

#define OFF_MEAN  (NROWS*DIM)            // 8388608
#define OFF_OUTER (NROWS*DIM + 1)
#define OFF_IDX   (NROWS*DIM + 1 + NQ)   // 8388613

typedef unsigned long long ull;
typedef unsigned int uint;

// ---------------- device scratch (no allocs allowed) ----------------
__device__ float  g_RES[NROWS*DIM];     // current residual
__device__ float  g_XN [NROWS*DIM];     // normalized residual (fp32)
__device__ float  g_RR [NROWS];         // ||residual||^2 per row
__device__ float2 g_CTP[NQ*128*NE];     // codebook, d-paired + transposed
__device__ float  g_CE [NQ*NE];         // ||e||^2
__device__ float  g_SEXP[KP];           // sum of exp(sim) per pair
__device__ float  g_POS [KP];           // pos logits
__device__ float  g_VQ  [NQ];           // sum of squared new residual
// bf16 row-major copies (16B aligned via uint4)
__device__ uint4  g_XNB4[NROWS*DIM/8];  // keys  [32768][256] bf16
__device__ uint4  g_QB4 [KP*DIM/8];     // queries [4096][256] bf16

// ---------------- helpers ----------------
__device__ __forceinline__ ull bc2(float a) {
    ull r; asm("mov.b64 %0, {%1, %1};" : "=l"(r) : "f"(a)); return r;
}
__device__ __forceinline__ float2 u2f(ull u) {
    float2 f;
    f.x = __uint_as_float((unsigned)(u & 0xffffffffu));
    f.y = __uint_as_float((unsigned)(u >> 32));
    return f;
}
__device__ __forceinline__ void fma2(ull &acc, ull a, ull b) {
    asm("fma.rn.f32x2 %0, %1, %2, %0;" : "+l"(acc) : "l"(a), "l"(b));
}
__device__ __forceinline__ uint smem_u32(const void* p) {
    return (uint)__cvta_generic_to_shared(p);
}
// pack two fp32 -> bf16x2 (lo = a, hi = b)
__device__ __forceinline__ uint pack_bf(float a, float b) {
    uint r; asm("cvt.rn.bf16x2.f32 %0, %1, %2;" : "=r"(r) : "f"(b), "f"(a));
    return r;
}
__device__ __forceinline__ void cp16(uint dst, const void* src) {
    asm volatile("cp.async.cg.shared.global [%0], [%1], 16;"
                 :: "r"(dst), "l"(src) : "memory");
}
__device__ __forceinline__ void ldm4(uint &r0, uint &r1, uint &r2, uint &r3, uint addr) {
    asm volatile("ldmatrix.sync.aligned.m8n8.x4.shared.b16 {%0,%1,%2,%3}, [%4];"
                 : "=r"(r0), "=r"(r1), "=r"(r2), "=r"(r3) : "r"(addr));
}
__device__ __forceinline__ void mma16816(float* c, const uint* a, const uint* b) {
    asm volatile(
        "mma.sync.aligned.m16n8k16.row.col.f32.bf16.bf16.f32 "
        "{%0,%1,%2,%3}, {%4,%5,%6,%7}, {%8,%9}, {%0,%1,%2,%3};"
        : "+f"(c[0]), "+f"(c[1]), "+f"(c[2]), "+f"(c[3])
        : "r"(a[0]), "r"(a[1]), "r"(a[2]), "r"(a[3]), "r"(b[0]), "r"(b[1]));
}

// block reduce (256 threads), result valid on thread 0
__device__ __forceinline__ float blockReduceSum256(float v, float* sbuf) {
    #pragma unroll
    for (int o = 16; o; o >>= 1) v += __shfl_down_sync(0xffffffffu, v, o);
    int w = threadIdx.x >> 5, l = threadIdx.x & 31;
    if (l == 0) sbuf[w] = v;
    __syncthreads();
    if (w == 0) {
        v = (l < 8) ? sbuf[l] : 0.f;
        #pragma unroll
        for (int o = 4; o; o >>= 1) v += __shfl_down_sync(0xffffffffu, v, o);
    }
    return v;
}

// ---------------- kernels ----------------

__global__ void k_init(const float* __restrict__ x) {
    int i = blockIdx.x * 256 + threadIdx.x;
    ((float4*)g_RES)[i] = ((const float4*)x)[i];
    if (i < NQ) g_VQ[i] = 0.f;
}

__global__ void k_prep(const float* __restrict__ CB) {
    __shared__ float sbuf[8];
    int q = blockIdx.y, j = blockIdx.x, d = threadIdx.x;
    const float* row = CB + ((size_t)q * NE + j) * DIM;
    float v = row[d];
    float s = blockReduceSum256(v * v, sbuf);
    if (d == 0) g_CE[q * NE + j] = s;
    if (d < 128) {
        float2 p; p.x = row[2*d]; p.y = row[2*d + 1];
        g_CTP[(q * 128 + d) * NE + j] = p;
    }
}

// normalize row; write fp32 XN and bf16 row-major copy
__global__ void k_norm() {
    __shared__ float sbuf[8];
    __shared__ float stot;
    __shared__ float rowv[DIM];
    int row = blockIdx.x, d = threadIdx.x;
    float v = g_RES[(size_t)row * DIM + d];
    float s = blockReduceSum256(v * v, sbuf);
    if (d == 0) { stot = s; g_RR[row] = s; }
    __syncthreads();
    float inv = rsqrtf(stot + 1e-12f);
    float xv = v * inv;
    g_XN[(size_t)row * DIM + d] = xv;
    rowv[d] = xv;
    __syncthreads();
    if (d < 128)
        ((uint*)g_XNB4)[(size_t)row * 128 + d] = pack_bf(rowv[2*d], rowv[2*d + 1]);
}

// gather queries -> bf16 row-major, compute pos (fp32), zero SEXP
__global__ void k_gather(const int* __restrict__ p1, const int* __restrict__ p2) {
    __shared__ float sbuf[8];
    __shared__ float rowv[DIM];
    int k = blockIdx.x, d = threadIdx.x;
    int i1 = p1[k], i2 = p2[k];
    float a = g_XN[(size_t)i1 * DIM + d];
    float b = g_XN[(size_t)i2 * DIM + d];
    rowv[d] = a;
    float s = blockReduceSum256(a * b, sbuf);
    if (d == 0) { g_POS[k] = s * 10.f; g_SEXP[k] = 0.f; }
    __syncthreads();
    if (d < 128)
        ((uint*)g_QB4)[(size_t)k * 128 + d] = pack_bf(rowv[2*d], rowv[2*d + 1]);
}

// ---------------- HMMA LSE GEMM ----------------
// CTA: 128 pairs x 128 keys x K=256 bf16, fp32 accum.
// 8 warps as 2(m) x 4(n); warp tile 64x32 = 4x4 m16n8k16.
// K chunks of 64, double-buffered cp.async, XOR-swizzled smem.
__global__ void __launch_bounds__(256, 2) k_lse_mma() {
    extern __shared__ char dyn[];
    uint sbase = smem_u32(dyn);

    int tid  = threadIdx.x;
    int wid  = tid >> 5, lane = tid & 31;
    int wm   = wid >> 2, wn   = wid & 3;
    int bn   = blockIdx.x, bm = blockIdx.y;

    const char* gA = (const char*)g_QB4  + (size_t)(bm * 128) * 512;
    const char* gB = (const char*)g_XNB4 + (size_t)(bn * 128) * 512;

    float acc[4][4][4];
    #pragma unroll
    for (int mt = 0; mt < 4; mt++)
        #pragma unroll
        for (int nt = 0; nt < 4; nt++)
            #pragma unroll
            for (int i = 0; i < 4; i++) acc[mt][nt][i] = 0.f;

    // chunk loader: 128 rows x 64 bf16 (128B/row) for A and B into buffer b
    auto load_chunk = [&](int kc, int b) {
        uint abuf = sbase + (uint)b * 32768u;
        uint bbuf = abuf + 16384u;
        #pragma unroll
        for (int t = 0; t < 4; t++) {
            int i = tid + t * 256;          // 0..1023
            int row = i >> 3, c = i & 7;
            uint soff = (uint)((row * 8 + (c ^ (row & 7))) * 16);
            const char* sa = gA + (size_t)row * 512 + kc * 128 + c * 16;
            const char* sb = gB + (size_t)row * 512 + kc * 128 + c * 16;
            cp16(abuf + soff, sa);
            cp16(bbuf + soff, sb);
        }
    };

    load_chunk(0, 0);
    asm volatile("cp.async.commit_group;" ::: "memory");
    load_chunk(1, 1);
    asm volatile("cp.async.commit_group;" ::: "memory");

    #pragma unroll
    for (int kc = 0; kc < 4; kc++) {
        if (kc < 3) asm volatile("cp.async.wait_group 1;" ::: "memory");
        else        asm volatile("cp.async.wait_group 0;" ::: "memory");
        __syncthreads();

        uint abuf = sbase + (uint)(kc & 1) * 32768u;
        uint bbuf = abuf + 16384u;

        #pragma unroll
        for (int ks = 0; ks < 4; ks++) {
            // A fragments: 4 m-tiles
            uint afr[4][4];
            #pragma unroll
            for (int mt = 0; mt < 4; mt++) {
                int row = wm * 64 + mt * 16 + (lane & 15);
                int chunk = ks * 2 + (lane >> 4);
                uint addr = abuf + (uint)((row * 8 + (chunk ^ (row & 7))) * 16);
                ldm4(afr[mt][0], afr[mt][1], afr[mt][2], afr[mt][3], addr);
            }
            // B fragments: 4 n-tiles via 2 x ldmatrix.x4
            uint bfr[4][2];
            #pragma unroll
            for (int p = 0; p < 2; p++) {
                int g = lane >> 3;
                int ntl = 2 * p + (g >> 1);
                int row = wn * 32 + ntl * 8 + (lane & 7);
                int chunk = ks * 2 + (g & 1);
                uint addr = bbuf + (uint)((row * 8 + (chunk ^ (row & 7))) * 16);
                ldm4(bfr[2*p][0], bfr[2*p][1], bfr[2*p+1][0], bfr[2*p+1][1], addr);
            }
            #pragma unroll
            for (int mt = 0; mt < 4; mt++)
                #pragma unroll
                for (int nt = 0; nt < 4; nt++)
                    mma16816(acc[mt][nt], afr[mt], bfr[nt]);
        }
        __syncthreads();
        if (kc < 2) {
            load_chunk(kc + 2, kc & 1);
            asm volatile("cp.async.commit_group;" ::: "memory");
        }
    }

    // epilogue: exp + row sums. rows: wm*64 + mt*16 + lane/4 (+8)
    float* red = (float*)dyn;   // 128 rows x 4 n-warps
    float s0[4], s1[4];
    #pragma unroll
    for (int mt = 0; mt < 4; mt++) {
        float a0 = 0.f, a1 = 0.f;
        #pragma unroll
        for (int nt = 0; nt < 4; nt++) {
            a0 += __expf(10.f * acc[mt][nt][0]) + __expf(10.f * acc[mt][nt][1]);
            a1 += __expf(10.f * acc[mt][nt][2]) + __expf(10.f * acc[mt][nt][3]);
        }
        #pragma unroll
        for (int o = 1; o < 4; o <<= 1) {
            a0 += __shfl_xor_sync(0xffffffffu, a0, o);
            a1 += __shfl_xor_sync(0xffffffffu, a1, o);
        }
        s0[mt] = a0; s1[mt] = a1;
    }
    __syncthreads();           // all warps done with smem buffers
    if ((lane & 3) == 0) {
        int rbase = wm * 64 + (lane >> 2);
        #pragma unroll
        for (int mt = 0; mt < 4; mt++) {
            red[(rbase + mt * 16)     * 4 + wn] = s0[mt];
            red[(rbase + mt * 16 + 8) * 4 + wn] = s1[mt];
        }
    }
    __syncthreads();
    if (tid < 128) {
        float s = red[tid * 4] + red[tid * 4 + 1] + red[tid * 4 + 2] + red[tid * 4 + 3];
        atomicAdd(&g_SEXP[bm * 128 + tid], s);
    }
}

__global__ void k_outer(float* __restrict__ out, int q) {
    __shared__ float sbuf[8];
    float acc = 0.f;
    for (int k = threadIdx.x; k < KP; k += 256)
        acc += logf(g_SEXP[k]) - g_POS[k];
    float s = blockReduceSum256(acc, sbuf);
    if (threadIdx.x == 0) out[OFF_OUTER + q] = s / (float)KP;
}

// quantize (reference-rounding-matched distances, fp32; unchanged)
__global__ void __launch_bounds__(256) k_quant(const float* __restrict__ CB,
                                               float* __restrict__ out,
                                               int q, int first) {
    __shared__ float rs[32][DIM];
    __shared__ ull   wmin[32][8];
    __shared__ int   idxs[32];
    __shared__ float sbuf[8];
    __shared__ float rr_s[32];

    int tid = threadIdx.x;
    int i0 = blockIdx.x * 32;

    #pragma unroll
    for (int i = 0; i < 8; i++) {
        int lin = tid + i * 256;
        int m = lin >> 6, c = lin & 63;
        ((float4*)&rs[m][0])[c] = *(const float4*)(g_RES + (size_t)(i0 + m) * DIM + c * 4);
    }
    if (tid < 32) rr_s[tid] = g_RR[i0 + tid];
    __syncthreads();

    int j = tid;
    ull dot2[32];
    #pragma unroll
    for (int m = 0; m < 32; m++) dot2[m] = 0ull;

    const float2* ctp = g_CTP + (size_t)q * 128 * NE;
    #pragma unroll 2
    for (int dpc = 0; dpc < 32; dpc++) {
        ull ct[4];
        #pragma unroll
        for (int c = 0; c < 4; c++)
            ct[c] = *(const ull*)&ctp[(dpc * 4 + c) * NE + j];
        #pragma unroll
        for (int m = 0; m < 32; m++) {
            #pragma unroll
            for (int c = 0; c < 4; c++) {
                ull r2 = *(const ull*)&rs[m][(dpc * 4 + c) * 2];
                fma2(dot2[m], r2, ct[c]);
            }
        }
    }

    float ce = g_CE[q * NE + j];
    #pragma unroll
    for (int m = 0; m < 32; m++) {
        float2 f = u2f(dot2[m]);
        float dotv = f.x + f.y;
        float t1 = fmaf(-2.f, dotv, rr_s[m]);
        float d2 = t1 + ce;
        unsigned u = __float_as_uint(d2);
        u = (u & 0x80000000u) ? ~u : (u | 0x80000000u);
        ull key = ((ull)u << 32) | (ull)(unsigned)j;
        #pragma unroll
        for (int o = 16; o; o >>= 1) {
            ull other = __shfl_down_sync(0xffffffffu, key, o);
            if (other < key) key = other;
        }
        if ((tid & 31) == 0) wmin[m][tid >> 5] = key;
    }
    __syncthreads();

    if (tid < 32) {
        ull best = wmin[tid][0];
        #pragma unroll
        for (int t = 1; t < 8; t++) if (wmin[tid][t] < best) best = wmin[tid][t];
        int id = (int)(best & 0xffu);
        idxs[tid] = id;
        out[OFF_IDX + (size_t)(i0 + tid) * NQ + q] = (float)id;
    }
    __syncthreads();

    const float* cb = CB + (size_t)q * NE * DIM;
    float ssq = 0.f;
    #pragma unroll 4
    for (int m = 0; m < 32; m++) {
        float cv = cb[(size_t)idxs[m] * DIM + tid];
        float nr = rs[m][tid] - cv;
        size_t go = (size_t)(i0 + m) * DIM + tid;
        g_RES[go] = nr;
        out[go] = first ? cv : (out[go] + cv);
        ssq += nr * nr;
    }
    float st = blockReduceSum256(ssq, sbuf);
    if (tid == 0) atomicAdd(&g_VQ[q], st);
}

__global__ void k_vqmean(float* __restrict__ out) {
    if (threadIdx.x == 0) {
        float s = g_VQ[0] + g_VQ[1] + g_VQ[2] + g_VQ[3];
        out[OFF_MEAN] = s * (1.25f / (4.f * (float)NROWS * (float)DIM));
    }
}

// ---------------- launch ----------------
extern "C" void kernel_launch(void* const* d_in, const int* in_sizes, int n_in,
                              void* d_out, int out_size) {
    const float* x  = (const float*)d_in[0];
    const float* cb = (const float*)d_in[1];
    const int*   p1 = (const int*)d_in[2];
    const int*   p2 = (const int*)d_in[3];
    float* out = (float*)d_out;

    cudaFuncSetAttribute(k_lse_mma, cudaFuncAttributeMaxDynamicSharedMemorySize, 65536);

    k_init<<<NROWS * DIM / 4 / 256, 256>>>(x);
    k_prep<<<dim3(NE, NQ), 256>>>(cb);
    for (int q = 0; q < NQ; q++) {
        k_norm<<<NROWS, 256>>>();
        k_gather<<<KP, 256>>>(p1, p2);
        k_lse_mma<<<dim3(NROWS / 128, KP / 128), 256, 65536>>>();
        k_outer<<<1, 256>>>(out, q);
        k_quant<<<NROWS / 32, 256>>>(cb, out, q, q == 0);
    }
    k_vqmean<<<1, 32>>>(out);
}